// round 11
// baseline (speedup 1.0000x reference)
#include <cuda_runtime.h>
#include <cstdint>

#define E_NUM 60000
#define LDX   3712          // 29 * 128, row stride of x and out

// tf32-rounded weights, [k][n] row-major (static device globals: allowed)
__device__ float g_w0[896 * 896];
__device__ float g_w1[1536 * 1536];
__device__ float g_w2[1280 * 1280];

__device__ __forceinline__ float to_tf32(float x) {
    uint32_t u;
    asm("cvt.rna.tf32.f32 %0, %1;" : "=r"(u) : "f"(x));
    return __uint_as_float(u);
}
__device__ __forceinline__ uint32_t s2u(const void* p) {
    uint32_t a;
    asm("{ .reg .u64 t; cvta.to.shared.u64 t, %1; cvt.u32.u64 %0, t; }" : "=r"(a) : "l"(p));
    return a;
}

// ---------------- weight prep (rna-rounded, [k][n]) ----------------

__global__ void prep_copy_k(const float* __restrict__ src, int n) {
    int i = blockIdx.x * blockDim.x + threadIdx.x;
    if (i < n) g_w0[i] = to_tf32(src[i]);
}
// W' = [[Wa, Wb], [-Wb, Wa]] (2H x 2H) from src (H x 2H), tf32-rounded.
__global__ void prep_so2_k(const float* __restrict__ src, int H, int which) {
    float* dst = (which == 1) ? g_w1 : g_w2;
    const int W2 = 2 * H;
    int i = blockIdx.x * blockDim.x + threadIdx.x;
    if (i >= W2 * W2) return;
    int k = i / W2;
    int n = i - k * W2;
    float v;
    if (k < H) {
        v = src[k * W2 + n];
    } else {
        int kk = k - H;
        v = (n < H) ? -src[kk * W2 + n + H] : src[kk * W2 + n - H];
    }
    dst[i] = to_tf32(v);
}

// ---------------- GEMM: C = A(ExK, ld LDX) * W(KxN) (+bias) ----------------
// Block tile 128x128x32, 128 threads (4 warps), warp grid 2x2, warp tile 64x64.
// 2 CTAs/SM. A: LDG->rna->STS in two halves (16 staging regs). B: cp.async
// (pre-rounded weights, no staging regs). BS_STRIDE=136 keeps B fragment
// loads conflict-free; AS_STRIDE=36 keeps A conflict-free.

#define AS_STRIDE 36
#define BS_STRIDE 136
#define AS_BUF (128 * AS_STRIDE)    // 4608 floats
#define BS_BUF (32 * BS_STRIDE)     // 4352 floats
#define SMEM_BYTES ((2 * AS_BUF + 2 * BS_BUF) * 4)   // 71680

__global__ __launch_bounds__(128, 2) void gemm_tf32_k(
    const float* __restrict__ A, const float* __restrict__ Bw,
    const float* __restrict__ bias, float* __restrict__ C,
    int N, int K)
{
    extern __shared__ float smem[];
    float* As = smem;                  // [2][128][36]
    float* Bs = smem + 2 * AS_BUF;     // [2][32][136]

    const int tid  = threadIdx.x;
    const int lane = tid & 31;
    const int warp = tid >> 5;         // 0..3
    const int wm   = warp >> 1;        // 0..1  (64-row strip)
    const int wn   = warp & 1;         // 0..1  (64-col strip)
    const int bn   = blockIdx.x;       // fastest: A tile L2-reused across N strip
    const int bm   = blockIdx.y;

    const int lr = lane >> 2;          // 0..7
    const int lc = lane & 3;           // 0..3

    float acc[4][8][4];
#pragma unroll
    for (int a = 0; a < 4; a++)
#pragma unroll
        for (int b = 0; b < 8; b++)
#pragma unroll
            for (int c = 0; c < 4; c++) acc[a][b][c] = 0.f;

    const int ar   = tid >> 3;         // A row base (0..15), rows ar + i*16
    const int asub = tid & 7;          // A 16B sub-chunk

    const int ktiles = K >> 5;

    float4 aReg[4];                    // one A half in flight at a time

    // A half h: rows ar + (i + 4h)*16, i = 0..3
    auto ldgA = [&](int kt, int h) {
#pragma unroll
        for (int i = 0; i < 4; i++) {
            int m = bm * 128 + ar + (i + 4 * h) * 16;
            if (m < E_NUM)
                aReg[i] = *reinterpret_cast<const float4*>(
                    A + (size_t)m * LDX + kt * 32 + asub * 4);
            else
                aReg[i] = make_float4(0.f, 0.f, 0.f, 0.f);
        }
    };
    auto stsA = [&](int buf, int h) {
        float* a = As + buf * AS_BUF;
#pragma unroll
        for (int i = 0; i < 4; i++) {
            float4 v = aReg[i];
            v.x = to_tf32(v.x); v.y = to_tf32(v.y);
            v.z = to_tf32(v.z); v.w = to_tf32(v.w);
            *reinterpret_cast<float4*>(
                a + (ar + (i + 4 * h) * 16) * AS_STRIDE + asub * 4) = v;
        }
    };
    // B tile 32 rows x 128 floats = 1024 x 16B chunks; 8 per thread via cp.async.
    auto cpaB = [&](int kt, int buf) {
#pragma unroll
        for (int i = 0; i < 8; i++) {
            int c = tid + i * 128;        // 0..1023
            int r = c >> 5;               // 0..31
            int sub = c & 31;             // 0..31
            uint32_t dst = s2u(Bs + buf * BS_BUF + r * BS_STRIDE + sub * 4);
            const float* src = Bw + (size_t)(kt * 32 + r) * N + bn * 128 + sub * 4;
            asm volatile("cp.async.cg.shared.global [%0], [%1], 16;"
                         :: "r"(dst), "l"(src) : "memory");
        }
        asm volatile("cp.async.commit_group;" ::: "memory");
    };
    auto compute_ks = [&](int buf, int ks) {
        const float* a = As + buf * AS_BUF;
        const float* b = Bs + buf * BS_BUF;
        const int k0 = ks * 8;
        uint32_t af[4][4];
#pragma unroll
        for (int im = 0; im < 4; im++) {
            int r  = wm * 64 + im * 16 + lr;
            int kc = k0 + lc;
            af[im][0] = __float_as_uint(a[r * AS_STRIDE + kc]);
            af[im][1] = __float_as_uint(a[(r + 8) * AS_STRIDE + kc]);
            af[im][2] = __float_as_uint(a[r * AS_STRIDE + kc + 4]);
            af[im][3] = __float_as_uint(a[(r + 8) * AS_STRIDE + kc + 4]);
        }
        uint32_t bf[8][2];
#pragma unroll
        for (int jn = 0; jn < 8; jn++) {
            int cn = wn * 64 + jn * 8 + lr;
            bf[jn][0] = __float_as_uint(b[(k0 + lc) * BS_STRIDE + cn]);
            bf[jn][1] = __float_as_uint(b[(k0 + 4 + lc) * BS_STRIDE + cn]);
        }
#pragma unroll
        for (int im = 0; im < 4; im++)
#pragma unroll
            for (int jn = 0; jn < 8; jn++) {
                asm volatile(
                    "mma.sync.aligned.m16n8k8.row.col.f32.tf32.tf32.f32 "
                    "{%0,%1,%2,%3}, {%4,%5,%6,%7}, {%8,%9}, {%0,%1,%2,%3};\n"
                    : "+f"(acc[im][jn][0]), "+f"(acc[im][jn][1]),
                      "+f"(acc[im][jn][2]), "+f"(acc[im][jn][3])
                    : "r"(af[im][0]), "r"(af[im][1]),
                      "r"(af[im][2]), "r"(af[im][3]),
                      "r"(bf[jn][0]), "r"(bf[jn][1]));
            }
    };

    // prologue
    cpaB(0, 0);
    ldgA(0, 0); stsA(0, 0);
    ldgA(0, 1); stsA(0, 1);
    asm volatile("cp.async.wait_group 0;" ::: "memory");
    __syncthreads();

    int buf = 0;
    for (int kt = 0; kt < ktiles; kt++) {
        const bool nxt = (kt + 1 < ktiles);
        if (nxt) { cpaB(kt + 1, buf ^ 1); ldgA(kt + 1, 0); }
        compute_ks(buf, 0);
        if (nxt) { stsA(buf ^ 1, 0); ldgA(kt + 1, 1); }
        compute_ks(buf, 1);
        compute_ks(buf, 2);
        if (nxt) stsA(buf ^ 1, 1);
        compute_ks(buf, 3);
        if (nxt) {
            asm volatile("cp.async.wait_group 0;" ::: "memory");
            __syncthreads();
        }
        buf ^= 1;
    }

    // epilogue
#pragma unroll
    for (int im = 0; im < 4; im++) {
        int r0 = bm * 128 + wm * 64 + im * 16 + lr;
#pragma unroll
        for (int jn = 0; jn < 8; jn++) {
            int cg = bn * 128 + wn * 64 + jn * 8 + lc * 2;
            float bv0 = 0.f, bv1 = 0.f;
            if (bias) { bv0 = bias[cg]; bv1 = bias[cg + 1]; }
            if (r0 < E_NUM) {
                float2 v; v.x = acc[im][jn][0] + bv0; v.y = acc[im][jn][1] + bv1;
                *reinterpret_cast<float2*>(C + (size_t)r0 * LDX + cg) = v;
            }
            if (r0 + 8 < E_NUM) {
                float2 v; v.x = acc[im][jn][2] + bv0; v.y = acc[im][jn][3] + bv1;
                *reinterpret_cast<float2*>(C + (size_t)(r0 + 8) * LDX + cg) = v;
            }
        }
    }
}

// ---------------- launch ----------------

extern "C" void kernel_launch(void* const* d_in, const int* in_sizes, int n_in,
                              void* d_out, int out_size)
{
    const float* x  = (const float*)d_in[0];
    // d_in[1] = x_edge: unused by the reference
    const float* w0 = (const float*)d_in[2];
    const float* b0 = (const float*)d_in[3];
    const float* w1 = (const float*)d_in[4];
    const float* w2 = (const float*)d_in[5];
    float* out = (float*)d_out;

    prep_copy_k<<<(896 * 896 + 255) / 256, 256>>>(w0, 896 * 896);
    prep_so2_k<<<(1536 * 1536 + 255) / 256, 256>>>(w1, 768, 1);
    prep_so2_k<<<(1280 * 1280 + 255) / 256, 256>>>(w2, 640, 2);

    float *pw0, *pw1, *pw2;
    cudaGetSymbolAddress((void**)&pw0, g_w0);
    cudaGetSymbolAddress((void**)&pw1, g_w1);
    cudaGetSymbolAddress((void**)&pw2, g_w2);

    cudaFuncSetAttribute(gemm_tf32_k,
                         cudaFuncAttributeMaxDynamicSharedMemorySize, SMEM_BYTES);

    const int mb = (E_NUM + 127) / 128;   // 469
    // m=0: (E,896) @ (896,896) + bias  -> out cols 0..895
    gemm_tf32_k<<<dim3(7, mb), 128, SMEM_BYTES>>>(x,        pw0, b0,      out,        896,  896);
    // m=1: (E,1536) @ (1536,1536)      -> out cols 896..2431
    gemm_tf32_k<<<dim3(12, mb), 128, SMEM_BYTES>>>(x + 896,  pw1, nullptr, out + 896,  1536, 1536);
    // m=2: (E,1280) @ (1280,1280)      -> out cols 2432..3711
    gemm_tf32_k<<<dim3(10, mb), 128, SMEM_BYTES>>>(x + 2432, pw2, nullptr, out + 2432, 1280, 1280);
}